// round 2
// baseline (speedup 1.0000x reference)
#include <cuda_runtime.h>
#include <cstdint>

// ---------------------------------------------------------------------------
// GLM4 MoE: T=512 tokens, H=2048 hidden, E=64 experts, top-k=8, I=768
// Shared expert treated as "expert 64" with all 512 tokens, weight 1.0.
// Strategy: fp32 router (exact top-k) -> per-expert token lists ->
//   TF32 mma.sync GEMMs (fp32 accumulate):
//     pass A: act = silu(x@w_gate) * (x@w_up)   (gather A rows, fused SwiGLU)
//     pass B: out += combine_w * (act @ w_down) (atomicAdd combine)
// ---------------------------------------------------------------------------

#define T_TOK 512
#define HDIM  2048
#define NEXP  64
#define TOPK  8
#define IDIM  768
#define NPAIR 4096            // T*K routed pairs
#define NROWS 4608            // + 512 shared rows

#define BM 128
#define BN 64
#define BK 32
#define ASTR 36               // A smem stride (floats): banks (4*row+col) conflict-free
#define BSTR 72               // B smem stride (floats): banks (8*k+n) conflict-free
#define A_STG (BM * ASTR)     // u32 per A stage = 4608
#define B_STG (BK * BSTR)     // u32 per B stage = 2304

#define SMEM_A_BYTES (2*A_STG*4 + 4*B_STG*4 + BM*4)          // 74240
#define SMEM_B_BYTES (2*A_STG*4 + 2*B_STG*4 + BM*4 + BM*4)   // 56320

// -------------------- scratch (static device globals, no allocs) -----------
__device__ int    g_topk_idx[NPAIR];
__device__ float  g_topk_w[NPAIR];
__device__ int    g_off[NEXP + 1];   // routed expert offsets; g_off[64] = 4096
__device__ int    g_ptok[NROWS];     // token id per pair-row
__device__ float  g_pw[NROWS];       // combine weight per pair-row
__device__ float  g_act[(size_t)NROWS * IDIM];   // ~14.2 MB SwiGLU activations

// -------------------- helpers ----------------------------------------------
__device__ __forceinline__ uint32_t f2tf(float f) {
    uint32_t u;
    asm("cvt.rna.tf32.f32 %0, %1;" : "=r"(u) : "f"(f));
    return u;
}

__device__ __forceinline__ void mma8(float c[4], const uint32_t a[4], const uint32_t b[2]) {
    asm volatile(
        "mma.sync.aligned.m16n8k8.row.col.f32.tf32.tf32.f32 "
        "{%0,%1,%2,%3}, {%4,%5,%6,%7}, {%8,%9}, {%0,%1,%2,%3};\n"
        : "+f"(c[0]), "+f"(c[1]), "+f"(c[2]), "+f"(c[3])
        : "r"(a[0]), "r"(a[1]), "r"(a[2]), "r"(a[3]),
          "r"(b[0]), "r"(b[1]));
}

// -------------------- kernel 1: router (exact fp32) -------------------------
__global__ __launch_bounds__(256) void k_router(const float* __restrict__ x,
                                                const float* __restrict__ gw,
                                                const float* __restrict__ gb) {
    __shared__ float xs[HDIM];
    __shared__ float lg[NEXP];
    int t = blockIdx.x, tid = threadIdx.x;
    const float4* xr = (const float4*)(x + (size_t)t * HDIM);
    for (int i = tid; i < HDIM / 4; i += 256) ((float4*)xs)[i] = xr[i];
    __syncthreads();

    int wid = tid >> 5, lane = tid & 31;
    int e0 = wid * 8;
    float acc[8] = {0.f,0.f,0.f,0.f,0.f,0.f,0.f,0.f};
    for (int i = 0; i < HDIM / 32; i++) {
        int h = i * 32 + lane;
        float xv = xs[h];
        #pragma unroll
        for (int j = 0; j < 8; j++) acc[j] += xv * gw[(e0 + j) * HDIM + h];
    }
    #pragma unroll
    for (int j = 0; j < 8; j++) {
        float v = acc[j];
        #pragma unroll
        for (int s = 16; s > 0; s >>= 1) v += __shfl_xor_sync(0xffffffffu, v, s);
        if (lane == 0) lg[e0 + j] = v;
    }
    __syncthreads();

    if (tid == 0) {
        float sc[NEXP];
        #pragma unroll 8
        for (int e = 0; e < NEXP; e++) sc[e] = 1.f / (1.f + expf(-lg[e]));
        unsigned long long used = 0ull;
        int idx[TOPK];
        float wsum = 0.f;
        for (int k = 0; k < TOPK; k++) {
            int am = 0; float bm = -1e30f;
            for (int e = 0; e < NEXP; e++) {
                if ((used >> e) & 1ull) continue;
                float b = sc[e] + gb[e];
                if (b > bm) { bm = b; am = e; }   // strict > == lowest index on ties
            }
            used |= (1ull << am);
            idx[k] = am;
            wsum += sc[am];
        }
        float inv = 1.f / (wsum + 1e-20f);
        for (int k = 0; k < TOPK; k++) {
            g_topk_idx[t * TOPK + k] = idx[k];
            g_topk_w[t * TOPK + k] = sc[idx[k]] * inv;
        }
    }
}

// -------------------- kernel 2: build per-expert token lists ----------------
__global__ __launch_bounds__(256) void k_build() {
    __shared__ int cnt[NEXP];
    __shared__ int offs[NEXP + 1];
    int tid = threadIdx.x;
    if (tid < NEXP) cnt[tid] = 0;
    __syncthreads();
    for (int p = tid; p < NPAIR; p += 256) atomicAdd(&cnt[g_topk_idx[p]], 1);
    __syncthreads();
    if (tid == 0) {
        int s = 0;
        for (int e = 0; e < NEXP; e++) { offs[e] = s; s += cnt[e]; }
        offs[NEXP] = s;   // == 4096
        for (int e = 0; e <= NEXP; e++) g_off[e] = offs[e];
    }
    __syncthreads();
    if (tid < NEXP) cnt[tid] = 0;
    __syncthreads();
    for (int p = tid; p < NPAIR; p += 256) {
        int e = g_topk_idx[p];
        int pos = atomicAdd(&cnt[e], 1);
        int dst = offs[e] + pos;
        g_ptok[dst] = p >> 3;         // token id
        g_pw[dst] = g_topk_w[p];
    }
    for (int r = tid; r < T_TOK; r += 256) {   // shared-expert rows
        g_ptok[NPAIR + r] = r;
        g_pw[NPAIR + r] = 1.0f;
    }
}

// -------------------- kernel 3: gate+up GEMM, fused SwiGLU ------------------
// grid: (IDIM/BN=12, 4 token-tiles, NEXP+1). block 256 = 8 warps:
//   warps 0-3 compute gate[wm*32..+32][0..64), warps 4-7 compute up (same rows)
__global__ __launch_bounds__(256) void k_gateup(
    const float* __restrict__ x,
    const float* __restrict__ w_gate, const float* __restrict__ w_up,
    const float* __restrict__ sw_gate, const float* __restrict__ sw_up) {
    int e = blockIdx.z;
    int off, n;
    const float *wg, *wu;
    if (e < NEXP) {
        off = g_off[e];
        n = g_off[e + 1] - off;
        size_t base = (size_t)e * HDIM * IDIM;
        wg = w_gate + base;
        wu = w_up + base;
    } else {
        off = NPAIR; n = T_TOK; wg = sw_gate; wu = sw_up;
    }
    int m0 = blockIdx.y * BM;
    if (m0 >= n) return;
    int i0 = blockIdx.x * BN;

    extern __shared__ unsigned char smem[];
    uint32_t* As = (uint32_t*)smem;                       // 2 stages x 128x36
    uint32_t* Bs = (uint32_t*)(smem + 2 * A_STG * 4);     // (stage,mat) x 32x72
    int* toks = (int*)(smem + 2 * A_STG * 4 + 4 * B_STG * 4);

    int tid = threadIdx.x;
    for (int r = tid; r < BM; r += 256)
        toks[r] = g_ptok[off + min(m0 + r, n - 1)];
    __syncthreads();

    float4 ra[4], rg[2], ru[2];
    auto load_tiles = [&](int k0) {
        #pragma unroll
        for (int j = 0; j < 4; j++) {
            int idx = tid + j * 256;
            int row = idx >> 3, seg = idx & 7;
            ra[j] = *(const float4*)(x + (size_t)toks[row] * HDIM + k0 + seg * 4);
        }
        #pragma unroll
        for (int j = 0; j < 2; j++) {
            int idx = tid + j * 256;
            int kr = idx >> 4, seg = idx & 15;
            size_t o = (size_t)(k0 + kr) * IDIM + i0 + seg * 4;
            rg[j] = *(const float4*)(wg + o);
            ru[j] = *(const float4*)(wu + o);
        }
    };
    auto store_tiles = [&](int nb) {
        uint32_t* Ad = As + nb * A_STG;
        #pragma unroll
        for (int j = 0; j < 4; j++) {
            int idx = tid + j * 256;
            int row = idx >> 3, seg = idx & 7;
            uint4 w;
            w.x = f2tf(ra[j].x); w.y = f2tf(ra[j].y);
            w.z = f2tf(ra[j].z); w.w = f2tf(ra[j].w);
            *(uint4*)(Ad + row * ASTR + seg * 4) = w;
        }
        uint32_t* Bg = Bs + (nb * 2 + 0) * B_STG;
        uint32_t* Bu = Bs + (nb * 2 + 1) * B_STG;
        #pragma unroll
        for (int j = 0; j < 2; j++) {
            int idx = tid + j * 256;
            int kr = idx >> 4, seg = idx & 15;
            uint4 w;
            w.x = f2tf(rg[j].x); w.y = f2tf(rg[j].y);
            w.z = f2tf(rg[j].z); w.w = f2tf(rg[j].w);
            *(uint4*)(Bg + kr * BSTR + seg * 4) = w;
            w.x = f2tf(ru[j].x); w.y = f2tf(ru[j].y);
            w.z = f2tf(ru[j].z); w.w = f2tf(ru[j].w);
            *(uint4*)(Bu + kr * BSTR + seg * 4) = w;
        }
    };

    int wid = tid >> 5, lane = tid & 31;
    int mat = wid >> 2, wm = wid & 3;
    int rbase = wm * 32;
    int g = lane >> 2, tg = lane & 3;

    float acc[2][8][4];
    #pragma unroll
    for (int a = 0; a < 2; a++)
        #pragma unroll
        for (int b = 0; b < 8; b++)
            #pragma unroll
            for (int c = 0; c < 4; c++) acc[a][b][c] = 0.f;

    load_tiles(0);
    store_tiles(0);
    __syncthreads();
    int buf = 0;
    for (int k0 = 0; k0 < HDIM; k0 += BK) {
        if (k0 + BK < HDIM) load_tiles(k0 + BK);
        const uint32_t* Ab = As + buf * A_STG;
        const uint32_t* Bb = Bs + (buf * 2 + mat) * B_STG;
        #pragma unroll
        for (int kk = 0; kk < 4; kk++) {
            int kc = kk * 8;
            uint32_t a[2][4];
            #pragma unroll
            for (int m2 = 0; m2 < 2; m2++) {
                int r0 = rbase + m2 * 16 + g;
                a[m2][0] = Ab[r0 * ASTR + kc + tg];
                a[m2][1] = Ab[(r0 + 8) * ASTR + kc + tg];
                a[m2][2] = Ab[r0 * ASTR + kc + tg + 4];
                a[m2][3] = Ab[(r0 + 8) * ASTR + kc + tg + 4];
            }
            uint32_t b[8][2];
            #pragma unroll
            for (int nt = 0; nt < 8; nt++) {
                b[nt][0] = Bb[(kc + tg) * BSTR + nt * 8 + g];
                b[nt][1] = Bb[(kc + tg + 4) * BSTR + nt * 8 + g];
            }
            #pragma unroll
            for (int m2 = 0; m2 < 2; m2++)
                #pragma unroll
                for (int nt = 0; nt < 8; nt++) mma8(acc[m2][nt], a[m2], b[nt]);
        }
        __syncthreads();
        if (k0 + BK < HDIM) store_tiles(buf ^ 1);
        __syncthreads();
        buf ^= 1;
    }

    // ---- epilogue: exchange gate via SMEM, fuse SwiGLU, coalesced store ----
    float* gbuf = (float*)smem;                         // 128 x stride 68
    float* abuf = (float*)(smem + 2 * A_STG * 4);       // 128 x stride 68
    if (mat == 0) {
        #pragma unroll
        for (int m2 = 0; m2 < 2; m2++)
            #pragma unroll
            for (int nt = 0; nt < 8; nt++) {
                int r0 = rbase + m2 * 16 + g;
                int c0 = nt * 8 + tg * 2;
                gbuf[r0 * 68 + c0]           = acc[m2][nt][0];
                gbuf[r0 * 68 + c0 + 1]       = acc[m2][nt][1];
                gbuf[(r0 + 8) * 68 + c0]     = acc[m2][nt][2];
                gbuf[(r0 + 8) * 68 + c0 + 1] = acc[m2][nt][3];
            }
    }
    __syncthreads();
    if (mat == 1) {
        #pragma unroll
        for (int m2 = 0; m2 < 2; m2++)
            #pragma unroll
            for (int nt = 0; nt < 8; nt++) {
                int r0 = rbase + m2 * 16 + g;
                int c0 = nt * 8 + tg * 2;
                #pragma unroll
                for (int c = 0; c < 4; c++) {
                    int row = r0 + ((c >= 2) ? 8 : 0);
                    int col = c0 + (c & 1);
                    float gv = gbuf[row * 68 + col];
                    float s = 1.f / (1.f + expf(-gv));
                    abuf[row * 68 + col] = gv * s * acc[m2][nt][c];
                }
            }
    }
    __syncthreads();
    int nr = min(BM, n - m0);
    for (int q = tid; q < nr * 16; q += 256) {
        int row = q >> 4, seg = q & 15;
        float4 v = *(float4*)(abuf + row * 68 + seg * 4);
        *(float4*)(g_act + (size_t)(off + m0 + row) * IDIM + i0 + seg * 4) = v;
    }
}

// -------------------- kernel 4: down GEMM + weighted combine ----------------
// grid: (HDIM/BN=32, 4 token-tiles, NEXP+1). 8 warps = 4(M) x 2(N).
__global__ __launch_bounds__(256) void k_down(
    const float* __restrict__ w_down, const float* __restrict__ sw_down,
    float* __restrict__ out) {
    int e = blockIdx.z;
    int off, n;
    const float* wd;
    if (e < NEXP) {
        off = g_off[e];
        n = g_off[e + 1] - off;
        wd = w_down + (size_t)e * IDIM * HDIM;
    } else {
        off = NPAIR; n = T_TOK; wd = sw_down;
    }
    int m0 = blockIdx.y * BM;
    if (m0 >= n) return;
    int h0 = blockIdx.x * BN;

    extern __shared__ unsigned char smem[];
    uint32_t* As = (uint32_t*)smem;
    uint32_t* Bs = (uint32_t*)(smem + 2 * A_STG * 4);
    int* toks = (int*)(smem + 2 * A_STG * 4 + 2 * B_STG * 4);
    float* wts = (float*)(toks + BM);

    int tid = threadIdx.x;
    for (int r = tid; r < BM; r += 256) {
        int src = off + min(m0 + r, n - 1);
        toks[r] = g_ptok[src];
        wts[r] = g_pw[src];
    }
    __syncthreads();

    float4 ra[4], rb[2];
    auto load_tiles = [&](int k0) {
        #pragma unroll
        for (int j = 0; j < 4; j++) {
            int idx = tid + j * 256;
            int row = idx >> 3, seg = idx & 7;
            int rgl = off + min(m0 + row, n - 1);
            ra[j] = *(const float4*)(g_act + (size_t)rgl * IDIM + k0 + seg * 4);
        }
        #pragma unroll
        for (int j = 0; j < 2; j++) {
            int idx = tid + j * 256;
            int kr = idx >> 4, seg = idx & 15;
            rb[j] = *(const float4*)(wd + (size_t)(k0 + kr) * HDIM + h0 + seg * 4);
        }
    };
    auto store_tiles = [&](int nb) {
        uint32_t* Ad = As + nb * A_STG;
        #pragma unroll
        for (int j = 0; j < 4; j++) {
            int idx = tid + j * 256;
            int row = idx >> 3, seg = idx & 7;
            uint4 w;
            w.x = f2tf(ra[j].x); w.y = f2tf(ra[j].y);
            w.z = f2tf(ra[j].z); w.w = f2tf(ra[j].w);
            *(uint4*)(Ad + row * ASTR + seg * 4) = w;
        }
        uint32_t* Bd = Bs + nb * B_STG;
        #pragma unroll
        for (int j = 0; j < 2; j++) {
            int idx = tid + j * 256;
            int kr = idx >> 4, seg = idx & 15;
            uint4 w;
            w.x = f2tf(rb[j].x); w.y = f2tf(rb[j].y);
            w.z = f2tf(rb[j].z); w.w = f2tf(rb[j].w);
            *(uint4*)(Bd + kr * BSTR + seg * 4) = w;
        }
    };

    int wid = tid >> 5, lane = tid & 31;
    int wm = wid & 3, wn = wid >> 2;
    int rbase = wm * 32, cbase = wn * 32;
    int g = lane >> 2, tg = lane & 3;

    float acc[2][4][4];
    #pragma unroll
    for (int a = 0; a < 2; a++)
        #pragma unroll
        for (int b = 0; b < 4; b++)
            #pragma unroll
            for (int c = 0; c < 4; c++) acc[a][b][c] = 0.f;

    load_tiles(0);
    store_tiles(0);
    __syncthreads();
    int buf = 0;
    for (int k0 = 0; k0 < IDIM; k0 += BK) {
        if (k0 + BK < IDIM) load_tiles(k0 + BK);
        const uint32_t* Ab = As + buf * A_STG;
        const uint32_t* Bb = Bs + buf * B_STG;
        #pragma unroll
        for (int kk = 0; kk < 4; kk++) {
            int kc = kk * 8;
            uint32_t a[2][4];
            #pragma unroll
            for (int m2 = 0; m2 < 2; m2++) {
                int r0 = rbase + m2 * 16 + g;
                a[m2][0] = Ab[r0 * ASTR + kc + tg];
                a[m2][1] = Ab[(r0 + 8) * ASTR + kc + tg];
                a[m2][2] = Ab[r0 * ASTR + kc + tg + 4];
                a[m2][3] = Ab[(r0 + 8) * ASTR + kc + tg + 4];
            }
            uint32_t b[4][2];
            #pragma unroll
            for (int nt = 0; nt < 4; nt++) {
                b[nt][0] = Bb[(kc + tg) * BSTR + cbase + nt * 8 + g];
                b[nt][1] = Bb[(kc + tg + 4) * BSTR + cbase + nt * 8 + g];
            }
            #pragma unroll
            for (int m2 = 0; m2 < 2; m2++)
                #pragma unroll
                for (int nt = 0; nt < 4; nt++) mma8(acc[m2][nt], a[m2], b[nt]);
        }
        __syncthreads();
        if (k0 + BK < IDIM) store_tiles(buf ^ 1);
        __syncthreads();
        buf ^= 1;
    }

    // ---- epilogue: weighted atomic combine into out ----
    #pragma unroll
    for (int m2 = 0; m2 < 2; m2++)
        #pragma unroll
        for (int nt = 0; nt < 4; nt++) {
            int r0 = rbase + m2 * 16 + g;
            int c0 = cbase + nt * 8 + tg * 2;
            #pragma unroll
            for (int c = 0; c < 4; c++) {
                int row = r0 + ((c >= 2) ? 8 : 0);
                int col = c0 + (c & 1);
                if (m0 + row < n) {
                    float v = acc[m2][nt][c] * wts[row];
                    atomicAdd(out + (size_t)toks[row] * HDIM + h0 + col, v);
                }
            }
        }
}

// -------------------- launcher ----------------------------------------------
extern "C" void kernel_launch(void* const* d_in, const int* in_sizes, int n_in,
                              void* d_out, int out_size) {
    const float* x       = (const float*)d_in[0];
    const float* gate_w  = (const float*)d_in[1];
    const float* gate_b  = (const float*)d_in[2];
    const float* w_gate  = (const float*)d_in[3];
    const float* w_up    = (const float*)d_in[4];
    const float* w_down  = (const float*)d_in[5];
    const float* sw_gate = (const float*)d_in[6];
    const float* sw_up   = (const float*)d_in[7];
    const float* sw_down = (const float*)d_in[8];
    float* out = (float*)d_out;

    cudaFuncSetAttribute(k_gateup, cudaFuncAttributeMaxDynamicSharedMemorySize, SMEM_A_BYTES);
    cudaFuncSetAttribute(k_down,   cudaFuncAttributeMaxDynamicSharedMemorySize, SMEM_B_BYTES);

    cudaMemsetAsync(d_out, 0, (size_t)T_TOK * HDIM * sizeof(float), 0);
    k_router<<<T_TOK, 256>>>(x, gate_w, gate_b);
    k_build<<<1, 256>>>();
    k_gateup<<<dim3(IDIM / BN, 4, NEXP + 1), 256, SMEM_A_BYTES>>>(x, w_gate, w_up, sw_gate, sw_up);
    k_down<<<dim3(HDIM / BN, 4, NEXP + 1), 256, SMEM_B_BYTES>>>(w_down, sw_down, out);
}

// round 5
// speedup vs baseline: 1.0575x; 1.0575x over previous
#include <cuda_runtime.h>
#include <cstdint>

// ---------------------------------------------------------------------------
// GLM4 MoE (sm_103 base ISA — tcgen05 unavailable in this toolchain's PTX pass)
// fp32 router -> per-expert lists -> TF32 mma.sync GEMMs with 64x64 warp
// tiles (0.125 operand-bytes/MAC: crossbar-balanced vs 0.25 before).
//   k_gateup: [128,2048] @ [2048, gate128|up128] -> SwiGLU -> g_act
//   k_down:   [128,768]  @ [768,256-tile of 2048] -> *w -> atomicAdd out
// ---------------------------------------------------------------------------

#define T_TOK 512
#define HDIM  2048
#define NEXP  64
#define TOPK  8
#define IDIM  768
#define NPAIR 4096
#define NROWS 4608

#define BM 128
#define BN 256
#define BK 32
#define ASTR 36      // (4*row+col) mod 32 bijective -> conflict-free A LDS
#define BSTR 264     // 264 mod 32 = 8 -> (8*k+n) pattern conflict-free B LDS
#define AS_FLT (BM * ASTR)          // 4608 floats per A stage
#define BS_FLT (BK * BSTR)          // 8448 floats per B stage
#define BS_OFF (2 * AS_FLT)         // B stages start (floats) = 9216
#define STAGE_END (BS_OFF + 2 * BS_FLT)   // 26112 floats = 104448 B
#define TOK_OFF STAGE_END
#define WTS_OFF (STAGE_END + 128)
#define EPI_STR 132
#define GU_SMEM (2 * 128 * EPI_STR * 4)   // 135168 (stages+toks fit inside)
#define DN_SMEM ((STAGE_END + 256) * 4)   // 105472

// -------------------- scratch ------------------------------------------------
__device__ int    g_topk_idx[NPAIR];
__device__ float  g_topk_w[NPAIR];
__device__ int    g_off[NEXP + 1];
__device__ int    g_ptok[NROWS];
__device__ float  g_pw[NROWS];
__device__ float  g_act[(size_t)NROWS * IDIM];

// -------------------- helpers ------------------------------------------------
__device__ __forceinline__ uint32_t f2tf(float f) {
    uint32_t u; asm("cvt.rna.tf32.f32 %0, %1;" : "=r"(u) : "f"(f)); return u;
}
__device__ __forceinline__ void mma8(float c[4], const uint32_t a[4], const uint32_t b[2]) {
    asm volatile(
        "mma.sync.aligned.m16n8k8.row.col.f32.tf32.tf32.f32 "
        "{%0,%1,%2,%3}, {%4,%5,%6,%7}, {%8,%9}, {%0,%1,%2,%3};\n"
        : "+f"(c[0]), "+f"(c[1]), "+f"(c[2]), "+f"(c[3])
        : "r"(a[0]), "r"(a[1]), "r"(a[2]), "r"(a[3]), "r"(b[0]), "r"(b[1]));
}

// -------------------- kernel 1: router (exact fp32) --------------------------
__global__ __launch_bounds__(256) void k_router(const float* __restrict__ x,
                                                const float* __restrict__ gw,
                                                const float* __restrict__ gb) {
    __shared__ float xs[HDIM];
    __shared__ float lg[NEXP];
    int t = blockIdx.x, tid = threadIdx.x;
    const float4* xr = (const float4*)(x + (size_t)t * HDIM);
    for (int i = tid; i < HDIM / 4; i += 256) ((float4*)xs)[i] = xr[i];
    __syncthreads();

    int wid = tid >> 5, lane = tid & 31;
    int e0 = wid * 8;
    float acc[8] = {0.f,0.f,0.f,0.f,0.f,0.f,0.f,0.f};
    for (int i = 0; i < HDIM / 32; i++) {
        int h = i * 32 + lane;
        float xv = xs[h];
        #pragma unroll
        for (int j = 0; j < 8; j++) acc[j] += xv * gw[(e0 + j) * HDIM + h];
    }
    #pragma unroll
    for (int j = 0; j < 8; j++) {
        float v = acc[j];
        #pragma unroll
        for (int s = 16; s > 0; s >>= 1) v += __shfl_xor_sync(0xffffffffu, v, s);
        if (lane == 0) lg[e0 + j] = v;
    }
    __syncthreads();

    if (tid == 0) {
        float sc[NEXP];
        #pragma unroll 8
        for (int e = 0; e < NEXP; e++) sc[e] = 1.f / (1.f + expf(-lg[e]));
        unsigned long long used = 0ull;
        int idx[TOPK];
        float wsum = 0.f;
        for (int k = 0; k < TOPK; k++) {
            int am = 0; float bm = -1e30f;
            for (int e = 0; e < NEXP; e++) {
                if ((used >> e) & 1ull) continue;
                float b = sc[e] + gb[e];
                if (b > bm) { bm = b; am = e; }
            }
            used |= (1ull << am);
            idx[k] = am;
            wsum += sc[am];
        }
        float inv = 1.f / (wsum + 1e-20f);
        for (int k = 0; k < TOPK; k++) {
            g_topk_idx[t * TOPK + k] = idx[k];
            g_topk_w[t * TOPK + k] = sc[idx[k]] * inv;
        }
    }
}

// -------------------- kernel 2: build per-expert token lists -----------------
__global__ __launch_bounds__(256) void k_build() {
    __shared__ int cnt[NEXP];
    __shared__ int offs[NEXP + 1];
    int tid = threadIdx.x;
    if (tid < NEXP) cnt[tid] = 0;
    __syncthreads();
    for (int p = tid; p < NPAIR; p += 256) atomicAdd(&cnt[g_topk_idx[p]], 1);
    __syncthreads();
    if (tid == 0) {
        int s = 0;
        for (int e = 0; e < NEXP; e++) { offs[e] = s; s += cnt[e]; }
        offs[NEXP] = s;
        for (int e = 0; e <= NEXP; e++) g_off[e] = offs[e];
    }
    __syncthreads();
    if (tid < NEXP) cnt[tid] = 0;
    __syncthreads();
    for (int p = tid; p < NPAIR; p += 256) {
        int e = g_topk_idx[p];
        int pos = atomicAdd(&cnt[e], 1);
        int dst = offs[e] + pos;
        g_ptok[dst] = p >> 3;
        g_pw[dst] = g_topk_w[p];
    }
    for (int r = tid; r < T_TOK; r += 256) {
        g_ptok[NPAIR + r] = r;
        g_pw[NPAIR + r] = 1.0f;
    }
}

// -------------------- kernel 3: gate+up GEMM + fused SwiGLU ------------------
// grid: (IDIM/128=6, 4 M-tiles, NEXP+1). 8 warps = 2(M)x4(N), warp 64x64.
// N=256 = [gate i0..i0+128 | up i0..i0+128].
__global__ __launch_bounds__(256, 1) void k_gateup(
    const float* __restrict__ x,
    const float* __restrict__ w_gate, const float* __restrict__ w_up,
    const float* __restrict__ sw_gate, const float* __restrict__ sw_up) {
    int e = blockIdx.z;
    int off, n; const float *wg, *wu;
    if (e < NEXP) {
        off = g_off[e]; n = g_off[e + 1] - off;
        size_t b0 = (size_t)e * HDIM * IDIM;
        wg = w_gate + b0; wu = w_up + b0;
    } else { off = NPAIR; n = T_TOK; wg = sw_gate; wu = sw_up; }
    int m0 = blockIdx.y * BM; if (m0 >= n) return;
    int i0 = blockIdx.x * 128;

    extern __shared__ float smf[];
    int* toks = (int*)(smf + TOK_OFF);
    int tid = threadIdx.x, wid = tid >> 5, lane = tid & 31;

    for (int r = tid; r < BM; r += 256) toks[r] = g_ptok[off + min(m0 + r, n - 1)];
    __syncthreads();
    int tokr[4];
    #pragma unroll
    for (int j = 0; j < 4; j++) tokr[j] = toks[(tid + j * 256) >> 3];

    int wm = wid & 1, wn = wid >> 1;
    int rbase = wm * 64, cbase = wn * 64;
    int g = lane >> 2, tg = lane & 3;

    float acc[4][8][4];
    #pragma unroll
    for (int a = 0; a < 4; a++)
        #pragma unroll
        for (int b = 0; b < 8; b++)
            #pragma unroll
            for (int c = 0; c < 4; c++) acc[a][b][c] = 0.f;

    float4 ra[4], rb[8];
    auto ldgA = [&](int kt) {
        int k0 = kt * BK;
        #pragma unroll
        for (int j = 0; j < 4; j++) {
            int seg = (tid + j * 256) & 7;
            ra[j] = *(const float4*)(x + (size_t)tokr[j] * HDIM + k0 + seg * 4);
        }
    };
    auto ldgB = [&](int kt) {
        int k0 = kt * BK;
        #pragma unroll
        for (int j = 0; j < 8; j++) {
            int idx = tid + j * 256;
            int kr = idx >> 6, seg = idx & 63;
            const float* w = (seg < 32) ? wg : wu;
            rb[j] = *(const float4*)(w + (size_t)(k0 + kr) * IDIM + i0 + (seg & 31) * 4);
        }
    };
    auto stsA = [&](int b) {
        uint32_t* Ad = (uint32_t*)smf + b * AS_FLT;
        #pragma unroll
        for (int j = 0; j < 4; j++) {
            int idx = tid + j * 256;
            int row = idx >> 3, seg = idx & 7;
            uint4 w;
            w.x = f2tf(ra[j].x); w.y = f2tf(ra[j].y); w.z = f2tf(ra[j].z); w.w = f2tf(ra[j].w);
            *(uint4*)(Ad + row * ASTR + seg * 4) = w;
        }
    };
    auto stsB = [&](int b) {
        uint32_t* Bd = (uint32_t*)smf + BS_OFF + b * BS_FLT;
        #pragma unroll
        for (int j = 0; j < 8; j++) {
            int idx = tid + j * 256;
            int kr = idx >> 6, seg = idx & 63;
            uint4 w;
            w.x = f2tf(rb[j].x); w.y = f2tf(rb[j].y); w.z = f2tf(rb[j].z); w.w = f2tf(rb[j].w);
            *(uint4*)(Bd + kr * BSTR + seg * 4) = w;
        }
    };
    auto frag_mma = [&](const uint32_t* Ab, const uint32_t* Bb, int kk) {
        int kc = kk * 8;
        uint32_t a[4][4];
        #pragma unroll
        for (int m2 = 0; m2 < 4; m2++) {
            int r0 = rbase + m2 * 16 + g;
            a[m2][0] = Ab[r0 * ASTR + kc + tg];
            a[m2][1] = Ab[(r0 + 8) * ASTR + kc + tg];
            a[m2][2] = Ab[r0 * ASTR + kc + tg + 4];
            a[m2][3] = Ab[(r0 + 8) * ASTR + kc + tg + 4];
        }
        uint32_t b[8][2];
        #pragma unroll
        for (int nb = 0; nb < 8; nb++) {
            int c0 = cbase + nb * 8 + g;
            b[nb][0] = Bb[(kc + tg) * BSTR + c0];
            b[nb][1] = Bb[(kc + tg + 4) * BSTR + c0];
        }
        #pragma unroll
        for (int m2 = 0; m2 < 4; m2++)
            #pragma unroll
            for (int nb = 0; nb < 8; nb++) mma8(acc[m2][nb], a[m2], b[nb]);
    };

    ldgA(0); ldgB(0); stsA(0); stsB(0);
    __syncthreads();
    const int NKT = HDIM / BK;   // 64
    for (int kt = 0; kt < NKT; kt++) {
        int b = kt & 1;
        bool more = (kt + 1 < NKT);
        if (more) ldgB(kt + 1);
        const uint32_t* Ab = (const uint32_t*)smf + b * AS_FLT;
        const uint32_t* Bb = (const uint32_t*)smf + BS_OFF + b * BS_FLT;
        frag_mma(Ab, Bb, 0);
        frag_mma(Ab, Bb, 1);
        if (more) ldgA(kt + 1);
        frag_mma(Ab, Bb, 2);
        frag_mma(Ab, Bb, 3);
        if (more) { stsA(b ^ 1); stsB(b ^ 1); }
        __syncthreads();
    }

    // ---- epilogue: gate warps dump -> up warps SwiGLU -> coalesced store ----
    float* gbuf = smf;
    float* abuf = smf + 128 * EPI_STR;
    if (wn < 2) {
        #pragma unroll
        for (int m2 = 0; m2 < 4; m2++)
            #pragma unroll
            for (int nb = 0; nb < 8; nb++) {
                int r0 = rbase + m2 * 16 + g;
                int c0 = cbase + nb * 8 + tg * 2;
                gbuf[r0 * EPI_STR + c0]           = acc[m2][nb][0];
                gbuf[r0 * EPI_STR + c0 + 1]       = acc[m2][nb][1];
                gbuf[(r0 + 8) * EPI_STR + c0]     = acc[m2][nb][2];
                gbuf[(r0 + 8) * EPI_STR + c0 + 1] = acc[m2][nb][3];
            }
    }
    __syncthreads();
    if (wn >= 2) {
        int ubase = (wn - 2) * 64;
        #pragma unroll
        for (int m2 = 0; m2 < 4; m2++)
            #pragma unroll
            for (int nb = 0; nb < 8; nb++) {
                int r0 = rbase + m2 * 16 + g;
                int c0 = ubase + nb * 8 + tg * 2;
                #pragma unroll
                for (int c = 0; c < 4; c++) {
                    int row = r0 + ((c >= 2) ? 8 : 0);
                    int col = c0 + (c & 1);
                    float gv = gbuf[row * EPI_STR + col];
                    float s = 1.f / (1.f + expf(-gv));
                    abuf[row * EPI_STR + col] = gv * s * acc[m2][nb][c];
                }
            }
    }
    __syncthreads();
    int nr = min(BM, n - m0);
    for (int q = tid; q < nr * 32; q += 256) {
        int row = q >> 5, seg = q & 31;
        float4 v = *(float4*)(abuf + row * EPI_STR + seg * 4);
        *(float4*)(g_act + (size_t)(off + m0 + row) * IDIM + i0 + seg * 4) = v;
    }
}

// -------------------- kernel 4: down GEMM + weighted combine -----------------
// grid: (HDIM/256=8, 4 M-tiles, NEXP+1). 8 warps = 2(M)x4(N), warp 64x64.
__global__ __launch_bounds__(256, 1) void k_down(
    const float* __restrict__ w_down, const float* __restrict__ sw_down,
    float* __restrict__ out) {
    int e = blockIdx.z;
    int off, n; const float* wd;
    if (e < NEXP) { off = g_off[e]; n = g_off[e + 1] - off; wd = w_down + (size_t)e * IDIM * HDIM; }
    else { off = NPAIR; n = T_TOK; wd = sw_down; }
    int m0 = blockIdx.y * BM; if (m0 >= n) return;
    int h0 = blockIdx.x * BN;

    extern __shared__ float smf[];
    int* toks = (int*)(smf + TOK_OFF);
    float* wts = smf + WTS_OFF;
    int tid = threadIdx.x, wid = tid >> 5, lane = tid & 31;

    for (int r = tid; r < BM; r += 256) {
        int s = off + min(m0 + r, n - 1);
        toks[r] = g_ptok[s];
        wts[r] = g_pw[s];
    }
    __syncthreads();
    int rowg[4];
    #pragma unroll
    for (int j = 0; j < 4; j++) rowg[j] = off + min(m0 + ((tid + j * 256) >> 3), n - 1);

    int wm = wid & 1, wn = wid >> 1;
    int rbase = wm * 64, cbase = wn * 64;
    int g = lane >> 2, tg = lane & 3;

    float acc[4][8][4];
    #pragma unroll
    for (int a = 0; a < 4; a++)
        #pragma unroll
        for (int b = 0; b < 8; b++)
            #pragma unroll
            for (int c = 0; c < 4; c++) acc[a][b][c] = 0.f;

    float4 ra[4], rb[8];
    auto ldgA = [&](int kt) {
        int k0 = kt * BK;
        #pragma unroll
        for (int j = 0; j < 4; j++) {
            int seg = (tid + j * 256) & 7;
            ra[j] = *(const float4*)(g_act + (size_t)rowg[j] * IDIM + k0 + seg * 4);
        }
    };
    auto ldgB = [&](int kt) {
        int k0 = kt * BK;
        #pragma unroll
        for (int j = 0; j < 8; j++) {
            int idx = tid + j * 256;
            int kr = idx >> 6, seg = idx & 63;
            rb[j] = *(const float4*)(wd + (size_t)(k0 + kr) * HDIM + h0 + seg * 4);
        }
    };
    auto stsA = [&](int b) {
        uint32_t* Ad = (uint32_t*)smf + b * AS_FLT;
        #pragma unroll
        for (int j = 0; j < 4; j++) {
            int idx = tid + j * 256;
            int row = idx >> 3, seg = idx & 7;
            uint4 w;
            w.x = f2tf(ra[j].x); w.y = f2tf(ra[j].y); w.z = f2tf(ra[j].z); w.w = f2tf(ra[j].w);
            *(uint4*)(Ad + row * ASTR + seg * 4) = w;
        }
    };
    auto stsB = [&](int b) {
        uint32_t* Bd = (uint32_t*)smf + BS_OFF + b * BS_FLT;
        #pragma unroll
        for (int j = 0; j < 8; j++) {
            int idx = tid + j * 256;
            int kr = idx >> 6, seg = idx & 63;
            uint4 w;
            w.x = f2tf(rb[j].x); w.y = f2tf(rb[j].y); w.z = f2tf(rb[j].z); w.w = f2tf(rb[j].w);
            *(uint4*)(Bd + kr * BSTR + seg * 4) = w;
        }
    };
    auto frag_mma = [&](const uint32_t* Ab, const uint32_t* Bb, int kk) {
        int kc = kk * 8;
        uint32_t a[4][4];
        #pragma unroll
        for (int m2 = 0; m2 < 4; m2++) {
            int r0 = rbase + m2 * 16 + g;
            a[m2][0] = Ab[r0 * ASTR + kc + tg];
            a[m2][1] = Ab[(r0 + 8) * ASTR + kc + tg];
            a[m2][2] = Ab[r0 * ASTR + kc + tg + 4];
            a[m2][3] = Ab[(r0 + 8) * ASTR + kc + tg + 4];
        }
        uint32_t b[8][2];
        #pragma unroll
        for (int nb = 0; nb < 8; nb++) {
            int c0 = cbase + nb * 8 + g;
            b[nb][0] = Bb[(kc + tg) * BSTR + c0];
            b[nb][1] = Bb[(kc + tg + 4) * BSTR + c0];
        }
        #pragma unroll
        for (int m2 = 0; m2 < 4; m2++)
            #pragma unroll
            for (int nb = 0; nb < 8; nb++) mma8(acc[m2][nb], a[m2], b[nb]);
    };

    ldgA(0); ldgB(0); stsA(0); stsB(0);
    __syncthreads();
    const int NKT = IDIM / BK;   // 24
    for (int kt = 0; kt < NKT; kt++) {
        int b = kt & 1;
        bool more = (kt + 1 < NKT);
        if (more) ldgB(kt + 1);
        const uint32_t* Ab = (const uint32_t*)smf + b * AS_FLT;
        const uint32_t* Bb = (const uint32_t*)smf + BS_OFF + b * BS_FLT;
        frag_mma(Ab, Bb, 0);
        frag_mma(Ab, Bb, 1);
        if (more) ldgA(kt + 1);
        frag_mma(Ab, Bb, 2);
        frag_mma(Ab, Bb, 3);
        if (more) { stsA(b ^ 1); stsB(b ^ 1); }
        __syncthreads();
    }

    // ---- epilogue: weighted atomic combine ----
    #pragma unroll
    for (int m2 = 0; m2 < 4; m2++) {
        #pragma unroll
        for (int nb = 0; nb < 8; nb++) {
            int r0 = rbase + m2 * 16 + g;
            int c0 = cbase + nb * 8 + tg * 2;
            #pragma unroll
            for (int c = 0; c < 4; c++) {
                int row = r0 + ((c >= 2) ? 8 : 0);
                int col = c0 + (c & 1);
                if (m0 + row < n) {
                    atomicAdd(out + (size_t)toks[row] * HDIM + h0 + col,
                              acc[m2][nb][c] * wts[row]);
                }
            }
        }
    }
}

// -------------------- launcher ----------------------------------------------
extern "C" void kernel_launch(void* const* d_in, const int* in_sizes, int n_in,
                              void* d_out, int out_size) {
    const float* x       = (const float*)d_in[0];
    const float* gate_w  = (const float*)d_in[1];
    const float* gate_b  = (const float*)d_in[2];
    const float* w_gate  = (const float*)d_in[3];
    const float* w_up    = (const float*)d_in[4];
    const float* w_down  = (const float*)d_in[5];
    const float* sw_gate = (const float*)d_in[6];
    const float* sw_up   = (const float*)d_in[7];
    const float* sw_down = (const float*)d_in[8];
    float* out = (float*)d_out;

    cudaFuncSetAttribute(k_gateup, cudaFuncAttributeMaxDynamicSharedMemorySize, GU_SMEM);
    cudaFuncSetAttribute(k_down,   cudaFuncAttributeMaxDynamicSharedMemorySize, DN_SMEM);

    cudaMemsetAsync(d_out, 0, (size_t)T_TOK * HDIM * sizeof(float), 0);
    k_router<<<T_TOK, 256>>>(x, gate_w, gate_b);
    k_build<<<1, 256>>>();
    k_gateup<<<dim3(IDIM / 128, 4, NEXP + 1), 256, GU_SMEM>>>(x, w_gate, w_up, sw_gate, sw_up);
    k_down<<<dim3(HDIM / BN, 4, NEXP + 1), 256, DN_SMEM>>>(w_down, sw_down, out);
}